// round 16
// baseline (speedup 1.0000x reference)
#include <cuda_runtime.h>
#include <cuda_fp16.h>
#include <cstdint>
#include <math.h>

#define BB 2
#define TQ 2048
#define TKV 2048
#define DD 2048
#define HQ 16
#define HKV 4
#define HD 128

// ======================= scratch =============================================
__device__ float g_tmp[BB * TQ * HQ * HD];    // Q-proj output (fp32)
__device__ float g_tmp2[BB * TKV * 1024];     // KV-proj output (fp32)
__device__ float2 g_trigq[BB * TQ * 64];
__device__ float2 g_trigk[BB * TKV * 64];
__device__ double g_invf[64];

__device__ __half g_k16[BB * HKV * TKV * HD];
__device__ __half g_v16[BB * HKV * TKV * HD];

__device__ __half g_xq16[BB * TQ * DD];
__device__ __half g_xk16[BB * TKV * DD];
__device__ __half g_w16q[DD * DD];
__device__ __half g_w16kv[1024 * DD];
__device__ __half g_w16o[DD * DD];

__device__ __half g_ct16[BB * TQ * DD];

// ======================= streams/events (static init) ========================
struct AsyncRes {
    cudaStream_t s1, s2;
    cudaEvent_t fork, e_wkv, e_q, e_trigk, e_misc, e_kv, e_qg, j1, j2;
    AsyncRes() {
        cudaStreamCreateWithFlags(&s1, cudaStreamNonBlocking);
        cudaStreamCreateWithFlags(&s2, cudaStreamNonBlocking);
        cudaEventCreateWithFlags(&fork, cudaEventDisableTiming);
        cudaEventCreateWithFlags(&e_wkv, cudaEventDisableTiming);
        cudaEventCreateWithFlags(&e_q, cudaEventDisableTiming);
        cudaEventCreateWithFlags(&e_trigk, cudaEventDisableTiming);
        cudaEventCreateWithFlags(&e_misc, cudaEventDisableTiming);
        cudaEventCreateWithFlags(&e_kv, cudaEventDisableTiming);
        cudaEventCreateWithFlags(&e_qg, cudaEventDisableTiming);
        cudaEventCreateWithFlags(&j1, cudaEventDisableTiming);
        cudaEventCreateWithFlags(&j2, cudaEventDisableTiming);
    }
};
static AsyncRes g_ar;

// ======================= small helpers =======================================
__device__ __forceinline__ uint32_t smem_u32(const void* p) {
    uint32_t a;
    asm("{ .reg .u64 t; cvta.to.shared.u64 t, %1; cvt.u32.u64 %0, t; }" : "=r"(a) : "l"(p));
    return a;
}
__device__ __forceinline__ void cp16(void* s, const void* g) {
    asm volatile("cp.async.cg.shared.global [%0], [%1], 16;"
                 :: "r"(smem_u32(s)), "l"(g));
}
#define CP_COMMIT() asm volatile("cp.async.commit_group;")
#define CP_WAIT0() asm volatile("cp.async.wait_group 0;")

__device__ __forceinline__ void ldm_x4(uint32_t* r, uint32_t addr) {
    asm volatile("ldmatrix.sync.aligned.m8n8.x4.shared.b16 {%0,%1,%2,%3}, [%4];"
                 : "=r"(r[0]), "=r"(r[1]), "=r"(r[2]), "=r"(r[3]) : "r"(addr));
}
__device__ __forceinline__ void ldm_x4_t(uint32_t* r, uint32_t addr) {
    asm volatile("ldmatrix.sync.aligned.m8n8.x4.trans.shared.b16 {%0,%1,%2,%3}, [%4];"
                 : "=r"(r[0]), "=r"(r[1]), "=r"(r[2]), "=r"(r[3]) : "r"(addr));
}
__device__ __forceinline__ void mma16816h(float* c, const uint32_t* a, uint32_t b0, uint32_t b1) {
    asm volatile("mma.sync.aligned.m16n8k16.row.col.f32.f16.f16.f32 "
                 "{%0,%1,%2,%3}, {%4,%5,%6,%7}, {%8,%9}, {%0,%1,%2,%3};"
                 : "+f"(c[0]), "+f"(c[1]), "+f"(c[2]), "+f"(c[3])
                 : "r"(a[0]), "r"(a[1]), "r"(a[2]), "r"(a[3]), "r"(b0), "r"(b1));
}
__device__ __forceinline__ uint32_t pack_h16(__half x, __half y) {
    uint16_t a = *(uint16_t*)&x, b = *(uint16_t*)&y;
    return (uint32_t)a | ((uint32_t)b << 16);
}
__device__ __forceinline__ uint32_t ex2_f16x2(float x, float y) {
    uint32_t pk, r;
    asm("cvt.rn.f16x2.f32 %0, %1, %2;" : "=r"(pk) : "f"(y), "f"(x));
    asm("ex2.approx.f16x2 %0, %1;" : "=r"(r) : "r"(pk));
    return r;
}
__device__ __forceinline__ float ex2f(float x) {
    float r;
    asm("ex2.approx.f32 %0, %1;" : "=f"(r) : "f"(x));
    return r;
}
__device__ __forceinline__ float2 unpack_h2(uint32_t v) {
    __half2 h = *reinterpret_cast<__half2*>(&v);
    return __half22float2(h);
}

// ======================= conversion kernels ==================================
__global__ void cvt_f16(const float* __restrict__ in, __half* __restrict__ h, int n) {
    int i = blockIdx.x * blockDim.x + threadIdx.x;
    if (i >= n) return;
    h[i] = __float2half(in[i]);
}

__global__ void splitT_h16(const float* __restrict__ in, __half* __restrict__ h,
                           int K, int N) {
    __shared__ float t[32][33];
    int tid = threadIdx.x;
    int kb = blockIdx.x * 32, nb = blockIdx.y * 32;
#pragma unroll
    for (int i = 0; i < 4; i++) {
        int e = tid + i * 256;
        int k = e >> 5, n = e & 31;
        t[k][n] = in[(size_t)(kb + k) * N + nb + n];
    }
    __syncthreads();
#pragma unroll
    for (int i = 0; i < 2; i++) {
        int e = tid + i * 256;
        int n = e >> 4, kp = (e & 15) * 2;
        uint32_t hi = pack_h16(__float2half(t[kp][n]), __float2half(t[kp + 1][n]));
        *(uint32_t*)&h[(size_t)(nb + n) * K + kb + kp] = hi;
    }
}

// ======================= 1-pass fp16 GEMM (64x64 warp tiles) =================
#define SP64 72
#define GEMM1_SMEM (2 * 2 * 128 * SP64 * 2)

__global__ __launch_bounds__(128, 2)
void gemm_h1(const __half* __restrict__ A, const __half* __restrict__ B,
             float* __restrict__ C, int M, int N, int K) {
    extern __shared__ __half sg1[];

    int tid = threadIdx.x;
    int lane = tid & 31, wid = tid >> 5;
    int wm = wid & 1, wn = wid >> 1;
    int m0 = blockIdx.y * 128;
    int n0 = blockIdx.x * 128;

    const int nit = K >> 6;

    auto issue = [&](int i) {
        __half* sb = sg1 + (i & 1) * 2 * 128 * SP64;
        const __half* Ag = A + (size_t)m0 * K + i * 64;
        const __half* Bg = B + (size_t)n0 * K + i * 64;
#pragma unroll
        for (int j = 0; j < 8; j++) {
            int id = tid + j * 128;
            int r = id >> 3, c8 = (id & 7) * 8;
            cp16(sb + r * SP64 + c8, Ag + (size_t)r * K + c8);
            cp16(sb + 128 * SP64 + r * SP64 + c8, Bg + (size_t)r * K + c8);
        }
    };

    float acc[4][8][4];
#pragma unroll
    for (int i = 0; i < 4; i++)
#pragma unroll
        for (int j = 0; j < 8; j++)
#pragma unroll
            for (int q = 0; q < 4; q++) acc[i][j][q] = 0.f;

    issue(0);
    CP_COMMIT();

    for (int i = 0; i < nit; i++) {
        CP_WAIT0();
        __syncthreads();
        if (i + 1 < nit) {
            issue(i + 1);
            CP_COMMIT();
        }
        __half* pA = sg1 + (i & 1) * 2 * 128 * SP64;
        __half* pB = pA + 128 * SP64;

#pragma unroll
        for (int ks = 0; ks < 64; ks += 16) {
            uint32_t ah[4][4], bh[4][4];
#pragma unroll
            for (int mt = 0; mt < 4; mt++) {
                int off = (wm * 64 + mt * 16 + (lane & 15)) * SP64 + ks + (lane >> 4) * 8;
                ldm_x4(ah[mt], smem_u32(pA + off));
            }
#pragma unroll
            for (int g = 0; g < 4; g++) {
                int boff = (wn * 64 + g * 16 + ((lane >> 4) << 3) + (lane & 7)) * SP64 +
                           ks + ((lane >> 3) & 1) * 8;
                ldm_x4(bh[g], smem_u32(pB + boff));
            }
#pragma unroll
            for (int g = 0; g < 4; g++)
#pragma unroll
                for (int pr = 0; pr < 2; pr++)
#pragma unroll
                    for (int mt = 0; mt < 4; mt++)
                        mma16816h(acc[mt][g * 2 + pr], ah[mt], bh[g][pr * 2], bh[g][pr * 2 + 1]);
        }
    }

#pragma unroll
    for (int mt = 0; mt < 4; mt++) {
        int r = m0 + wm * 64 + mt * 16 + (lane >> 2);
#pragma unroll
        for (int nt = 0; nt < 8; nt++) {
            int cidx = n0 + wn * 64 + nt * 8 + (lane & 3) * 2;
            *(float2*)&C[(size_t)r * N + cidx] = make_float2(acc[mt][nt][0], acc[mt][nt][1]);
            *(float2*)&C[(size_t)(r + 8) * N + cidx] = make_float2(acc[mt][nt][2], acc[mt][nt][3]);
        }
    }
}

// ======================= RoPE / transpose ====================================
__global__ void freq_kernel(double* __restrict__ invf) {
    int d = threadIdx.x;
    if (d < 64) invf[d] = pow(10000.0, -(double)d / 64.0);
}

__global__ void trig_kernel(const int* __restrict__ pos, const double* __restrict__ invf,
                            float2* __restrict__ out, int total) {
    int i = blockIdx.x * blockDim.x + threadIdx.x;
    if (i >= total) return;
    int d = i & 63;
    int bt = i >> 6;
    double ang = (double)pos[bt] * invf[d];
    double k = rint(ang * 0.15915494309189535);
    double r = fma(-k, 6.283185307179586, ang);
    r = fma(-k, 2.4492935982947064e-16, r);
    float rf = (float)r;
    float s, c;
    sincosf(rf, &s, &c);
    out[i] = make_float2(s, c);
}

// Fused K rope + V transpose from tmp2 (stride 1024: K cols 0-511, V cols 512-1023)
__global__ void ropekv16(const float* __restrict__ in, const float2* __restrict__ trig,
                         __half* __restrict__ k16, __half* __restrict__ v16) {
    int idx = blockIdx.x * blockDim.x + threadIdx.x;
    int total = BB * TKV * HKV * 64;
    if (idx >= total) return;
    int d = idx & 63;
    int h = (idx >> 6) & 3;
    int bt = idx >> 8;
    int b = bt / TKV, t = bt % TKV;

    const float* row = in + (size_t)bt * 1024;
    float x1 = row[h * HD + d];
    float x2 = row[h * HD + d + 64];
    float2 sc = trig[(size_t)bt * 64 + d];
    size_t o = ((size_t)(b * HKV + h) * TKV + t) * HD + d;
    k16[o] = __float2half(x1 * sc.y - x2 * sc.x);
    k16[o + 64] = __float2half(x1 * sc.x + x2 * sc.y);

    float v1 = row[512 + h * HD + d];
    float v2 = row[512 + h * HD + d + 64];
    v16[o] = __float2half(v1);
    v16[o + 64] = __float2half(v2);
}

// ======================= Flash attention (fused Q-rope) ======================
// Q read as fp32 proj output + trig, rope applied while filling sQ.
#define RS 136
#define ATTN2_SMEM ((128 * RS + 2 * 2 * 64 * RS) * 2)

__global__ __launch_bounds__(256, 1)
void attn_mma(const float* __restrict__ Qf, const float2* __restrict__ trigq,
              const __half* __restrict__ K16, const __half* __restrict__ V16,
              __half* __restrict__ C16, int qt_off) {
    extern __shared__ __half smh[];
    __half* sQ = smh;
    __half* sKV = smh + 128 * RS;

    int tid = threadIdx.x, lane = tid & 31, wm = tid >> 5;
    int qt = qt_off + (gridDim.x - 1 - blockIdx.x);
    int h = blockIdx.y, b = blockIdx.z;
    int qs0 = qt * 128;
    int bT = b * TQ;
    size_t kvoff = (size_t)(b * HKV + (h >> 2)) * TKV * HD;
    const __half* k_b = K16 + kvoff;
    const __half* v_b = V16 + kvoff;

    auto issueKV = [&](int jt) {
        __half* base = sKV + (jt & 1) * 2 * 64 * RS;
        const __half* kk = k_b + (size_t)jt * 64 * HD;
        const __half* vv = v_b + (size_t)jt * 64 * HD;
#pragma unroll
        for (int i = 0; i < 4; i++) {
            int c = tid + i * 256;
            int r = c >> 4, c8 = (c & 15) * 8;
            int so = r * RS + c8;
            size_t go = (size_t)r * HD + c8;
            cp16(base + so, kk + go);
            cp16(base + 64 * RS + so, vv + go);
        }
    };

    issueKV(0);
    CP_COMMIT();

    // ---- Q load with fused rope (fp32 -> fp16) ----
    {
        const float* qbase = Qf + (size_t)(bT + qs0) * DD + h * HD;
#pragma unroll 8
        for (int i = 0; i < 32; i++) {
            int idx = tid + i * 256;
            int d = idx & 63, r = idx >> 6;
            const float* rp = qbase + (size_t)r * DD;
            float x1 = rp[d], x2 = rp[d + 64];
            float2 sc = trigq[(size_t)(bT + qs0 + r) * 64 + d];
            sQ[r * RS + d] = __float2half(x1 * sc.y - x2 * sc.x);
            sQ[r * RS + d + 64] = __float2half(x1 * sc.x + x2 * sc.y);
        }
    }

    float o[16][4];
#pragma unroll
    for (int i = 0; i < 16; i++)
#pragma unroll
        for (int j = 0; j < 4; j++) o[i][j] = 0.f;
    float m0 = -1e30f, m1 = -1e30f, l0 = 0.f, l1 = 0.f;

    const float scale2 = 0.08838834764831845f * 1.4426950408889634f;
    int row0 = qs0 + wm * 16 + (lane >> 2);
    int ntiles = 2 * (qt + 1);

    for (int jt = 0; jt < ntiles; jt++) {
        CP_WAIT0();
        __syncthreads();
        if (jt + 1 < ntiles) {
            issueKV(jt + 1);
            CP_COMMIT();
        }
        __half* kk = sKV + (jt & 1) * 2 * 64 * RS;
        __half* vv = kk + 64 * RS;

        float s_[8][4];
#pragma unroll
        for (int i = 0; i < 8; i++)
#pragma unroll
            for (int j = 0; j < 4; j++) s_[i][j] = 0.f;

#pragma unroll
        for (int kt = 0; kt < 8; kt++) {
            uint32_t ah[4], bh[4][4];
            int arow = (wm * 16 + (lane & 15)) * RS + kt * 16 + (lane >> 4) * 8;
            ldm_x4(ah, smem_u32(&sQ[arow]));
#pragma unroll
            for (int g = 0; g < 4; g++) {
                int boff = (g * 16 + ((lane >> 4) << 3) + (lane & 7)) * RS +
                           kt * 16 + ((lane >> 3) & 1) * 8;
                ldm_x4(bh[g], smem_u32(&kk[boff]));
            }
#pragma unroll
            for (int g = 0; g < 4; g++)
#pragma unroll
                for (int pr = 0; pr < 2; pr++)
                    mma16816h(s_[g * 2 + pr], ah, bh[g][pr * 2], bh[g][pr * 2 + 1]);
        }

#pragma unroll
        for (int nt = 0; nt < 8; nt++)
#pragma unroll
            for (int c = 0; c < 4; c++) s_[nt][c] *= scale2;
        if (jt * 64 + 63 > row0) {
#pragma unroll
            for (int nt = 0; nt < 8; nt++) {
                int colb = jt * 64 + nt * 8 + (lane & 3) * 2;
                if (colb > row0) s_[nt][0] = -1e30f;
                if (colb + 1 > row0) s_[nt][1] = -1e30f;
                if (colb > row0 + 8) s_[nt][2] = -1e30f;
                if (colb + 1 > row0 + 8) s_[nt][3] = -1e30f;
            }
        }

        float tm0 = -1e30f, tm1 = -1e30f;
#pragma unroll
        for (int nt = 0; nt < 8; nt++) {
            tm0 = fmaxf(tm0, fmaxf(s_[nt][0], s_[nt][1]));
            tm1 = fmaxf(tm1, fmaxf(s_[nt][2], s_[nt][3]));
        }
        tm0 = fmaxf(tm0, __shfl_xor_sync(0xffffffffu, tm0, 1));
        tm0 = fmaxf(tm0, __shfl_xor_sync(0xffffffffu, tm0, 2));
        tm1 = fmaxf(tm1, __shfl_xor_sync(0xffffffffu, tm1, 1));
        tm1 = fmaxf(tm1, __shfl_xor_sync(0xffffffffu, tm1, 2));
        float nm0 = fmaxf(m0, tm0), nm1 = fmaxf(m1, tm1);
        float a0 = ex2f(m0 - nm0), a1 = ex2f(m1 - nm1);

        uint32_t pf[4][4];
        float rs0 = 0.f, rs1 = 0.f;
#pragma unroll
        for (int kt = 0; kt < 4; kt++) {
            pf[kt][0] = ex2_f16x2(s_[2 * kt][0] - nm0, s_[2 * kt][1] - nm0);
            pf[kt][1] = ex2_f16x2(s_[2 * kt][2] - nm1, s_[2 * kt][3] - nm1);
            pf[kt][2] = ex2_f16x2(s_[2 * kt + 1][0] - nm0, s_[2 * kt + 1][1] - nm0);
            pf[kt][3] = ex2_f16x2(s_[2 * kt + 1][2] - nm1, s_[2 * kt + 1][3] - nm1);
            float2 f;
            f = unpack_h2(pf[kt][0]); rs0 += f.x + f.y;
            f = unpack_h2(pf[kt][2]); rs0 += f.x + f.y;
            f = unpack_h2(pf[kt][1]); rs1 += f.x + f.y;
            f = unpack_h2(pf[kt][3]); rs1 += f.x + f.y;
        }
        rs0 += __shfl_xor_sync(0xffffffffu, rs0, 1);
        rs0 += __shfl_xor_sync(0xffffffffu, rs0, 2);
        rs1 += __shfl_xor_sync(0xffffffffu, rs1, 1);
        rs1 += __shfl_xor_sync(0xffffffffu, rs1, 2);
        l0 = l0 * a0 + rs0;
        l1 = l1 * a1 + rs1;
        m0 = nm0;
        m1 = nm1;
#pragma unroll
        for (int nt = 0; nt < 16; nt++) {
            o[nt][0] *= a0;
            o[nt][1] *= a0;
            o[nt][2] *= a1;
            o[nt][3] *= a1;
        }

#pragma unroll
        for (int kt = 0; kt < 4; kt++) {
            int vrow = kt * 16 + (lane & 7) + ((lane >> 3) & 1) * 8;
#pragma unroll
            for (int g = 0; g < 8; g++) {
                uint32_t vhf[4];
                int voff = vrow * RS + g * 16 + (lane >> 4) * 8;
                ldm_x4_t(vhf, smem_u32(&vv[voff]));
                mma16816h(o[2 * g], pf[kt], vhf[0], vhf[1]);
                mma16816h(o[2 * g + 1], pf[kt], vhf[2], vhf[3]);
            }
        }
    }

    float li0 = 1.0f / l0, li1 = 1.0f / l1;
#pragma unroll
    for (int nt = 0; nt < 16; nt++) {
        int col = nt * 8 + (lane & 3) * 2;
        size_t ad0 = ((size_t)(bT + row0) * HQ + h) * HD + col;
        size_t ad1 = ((size_t)(bT + row0 + 8) * HQ + h) * HD + col;
        *(uint32_t*)&C16[ad0] =
            pack_h16(__float2half(o[nt][0] * li0), __float2half(o[nt][1] * li0));
        *(uint32_t*)&C16[ad1] =
            pack_h16(__float2half(o[nt][2] * li1), __float2half(o[nt][3] * li1));
    }
}

// ======================= launch ==============================================
extern "C" void kernel_launch(void* const* d_in, const int* in_sizes, int n_in,
                              void* d_out, int out_size) {
    const float* Xq  = (const float*)d_in[0];
    const float* Xkv = (const float*)d_in[1];
    const float* Wq  = (const float*)d_in[2];
    const float* Wk  = (const float*)d_in[3];
    const float* Wv  = (const float*)d_in[4];
    const float* Wo  = (const float*)d_in[5];
    const int* qpos  = (const int*)d_in[6];
    const int* kpos  = (const int*)d_in[7];
    float* out = (float*)d_out;

    void* p;
    cudaGetSymbolAddress(&p, g_tmp); float* tmp = (float*)p;
    cudaGetSymbolAddress(&p, g_tmp2); float* tmp2 = (float*)p;
    cudaGetSymbolAddress(&p, g_trigq); float2* trigq = (float2*)p;
    cudaGetSymbolAddress(&p, g_trigk); float2* trigk = (float2*)p;
    cudaGetSymbolAddress(&p, g_invf); double* invf = (double*)p;
    __half *k16, *v16, *xq16, *xk16, *w16q, *w16kv, *w16o, *ct16;
    cudaGetSymbolAddress(&p, g_k16); k16 = (__half*)p;
    cudaGetSymbolAddress(&p, g_v16); v16 = (__half*)p;
    cudaGetSymbolAddress(&p, g_xq16); xq16 = (__half*)p;
    cudaGetSymbolAddress(&p, g_xk16); xk16 = (__half*)p;
    cudaGetSymbolAddress(&p, g_w16q); w16q = (__half*)p;
    cudaGetSymbolAddress(&p, g_w16kv); w16kv = (__half*)p;
    cudaGetSymbolAddress(&p, g_w16o); w16o = (__half*)p;
    cudaGetSymbolAddress(&p, g_ct16); ct16 = (__half*)p;

    cudaFuncSetAttribute(attn_mma, cudaFuncAttributeMaxDynamicSharedMemorySize, ATTN2_SMEM);
    cudaFuncSetAttribute(gemm_h1, cudaFuncAttributeMaxDynamicSharedMemorySize, GEMM1_SMEM);

    const int M = BB * TQ;  // 4096
    int nX = BB * TQ * DD;
    cudaStream_t s0 = 0, s1 = g_ar.s1, s2 = g_ar.s2;

    // ---- fork ----
    cudaEventRecord(g_ar.fork, s0);
    cudaStreamWaitEvent(s1, g_ar.fork, 0);
    cudaStreamWaitEvent(s2, g_ar.fork, 0);

    // head: only cvt(Xkv)+Wk/Wv-T gate the first GEMM
    cvt_f16<<<(nX + 255) / 256, 256, 0, s0>>>(Xkv, xk16, nX);
    splitT_h16<<<dim3(DD / 32, 512 / 32), 256, 0, s2>>>(Wk, w16kv, DD, 512);
    splitT_h16<<<dim3(DD / 32, 512 / 32), 256, 0, s2>>>(Wv, w16kv + 512 * DD, DD, 512);
    cudaEventRecord(g_ar.e_wkv, s2);
    cudaStreamWaitEvent(s0, g_ar.e_wkv, 0);

    // ---- KV projection (first tensor op) ----                 (profiled slot)
    gemm_h1<<<dim3(1024 / 128, M / 128), 128, GEMM1_SMEM, s0>>>(xk16, w16kv, tmp2, M, 1024, DD);
    cudaEventRecord(g_ar.e_kv, s0);

    // s1: Q-side conversions (run under KV-GEMM)
    cvt_f16<<<(nX + 255) / 256, 256, 0, s1>>>(Xq, xq16, nX);
    splitT_h16<<<dim3(DD / 32, DD / 32), 256, 0, s1>>>(Wq, w16q, DD, DD);
    cudaEventRecord(g_ar.e_q, s1);

    // s2: trig/Wo (input-only)
    freq_kernel<<<1, 64, 0, s2>>>(invf);
    trig_kernel<<<(BB * TKV * 64 + 255) / 256, 256, 0, s2>>>(kpos, invf, trigk, BB * TKV * 64);
    cudaEventRecord(g_ar.e_trigk, s2);
    trig_kernel<<<(BB * TQ * 64 + 255) / 256, 256, 0, s2>>>(qpos, invf, trigq, BB * TQ * 64);
    splitT_h16<<<dim3(HQ * HD / 32, DD / 32), 256, 0, s2>>>(Wo, w16o, HQ * HD, DD);
    cudaEventRecord(g_ar.e_misc, s2);

    // s1: fused K-rope + V-transpose, overlapping Q-GEMM
    cudaStreamWaitEvent(s1, g_ar.e_kv, 0);
    cudaStreamWaitEvent(s1, g_ar.e_trigk, 0);
    ropekv16<<<(BB * TKV * HKV * 64 + 255) / 256, 256, 0, s1>>>(tmp2, trigk, k16, v16);
    cudaEventRecord(g_ar.j1, s1);

    // ---- Q projection ----
    cudaStreamWaitEvent(s0, g_ar.e_q, 0);
    gemm_h1<<<dim3(DD / 128, M / 128), 128, GEMM1_SMEM, s0>>>(xq16, w16q, tmp, M, DD, DD);
    cudaEventRecord(g_ar.e_qg, s0);

    // ---- attention heavy half (qt 8..15) on s0 ----
    cudaStreamWaitEvent(s0, g_ar.j1, 0);
    cudaStreamWaitEvent(s0, g_ar.e_misc, 0);
    attn_mma<<<dim3(8, HQ, BB), 256, ATTN2_SMEM, s0>>>(tmp, trigq, k16, v16, ct16, 8);

    // ---- attention light half (qt 0..7) on s1, concurrent ----
    cudaStreamWaitEvent(s1, g_ar.e_qg, 0);
    cudaStreamWaitEvent(s1, g_ar.e_misc, 0);
    attn_mma<<<dim3(8, HQ, BB), 256, ATTN2_SMEM, s1>>>(tmp, trigq, k16, v16, ct16, 0);

    // ---- O-projection, pipelined halves ----
    // heavy rows: t in [1024,2048) per batch -> row offsets 1024 and 3072
    gemm_h1<<<dim3(DD / 128, 8), 128, GEMM1_SMEM, s0>>>(
        ct16 + (size_t)1024 * DD, w16o, out + (size_t)1024 * DD, 1024, DD, DD);
    gemm_h1<<<dim3(DD / 128, 8), 128, GEMM1_SMEM, s0>>>(
        ct16 + (size_t)3072 * DD, w16o, out + (size_t)3072 * DD, 1024, DD, DD);
    // light rows: t in [0,1024) per batch -> row offsets 0 and 2048
    gemm_h1<<<dim3(DD / 128, 8), 128, GEMM1_SMEM, s1>>>(
        ct16, w16o, out, 1024, DD, DD);
    gemm_h1<<<dim3(DD / 128, 8), 128, GEMM1_SMEM, s1>>>(
        ct16 + (size_t)2048 * DD, w16o, out + (size_t)2048 * DD, 1024, DD, DD);

    // ---- final join ----
    cudaEventRecord(g_ar.j2, s1);
    cudaStreamWaitEvent(s0, g_ar.j2, 0);
}

// round 17
// speedup vs baseline: 1.5020x; 1.5020x over previous
#include <cuda_runtime.h>
#include <cuda_fp16.h>
#include <cstdint>
#include <math.h>

#define BB 2
#define TQ 2048
#define TKV 2048
#define DD 2048
#define HQ 16
#define HKV 4
#define HD 128

// ======================= scratch =============================================
__device__ float g_tmp[BB * TQ * HQ * HD];    // Q-proj output (fp32)
__device__ float g_tmp2[BB * TKV * 1024];     // KV-proj output (fp32)
__device__ float2 g_trigq[BB * TQ * 64];
__device__ float2 g_trigk[BB * TKV * 64];
__device__ double g_invf[64];

__device__ __half g_k16[BB * HKV * TKV * HD];
__device__ __half g_v16[BB * HKV * TKV * HD];

__device__ __half g_xq16[BB * TQ * DD];
__device__ __half g_xk16[BB * TKV * DD];
__device__ __half g_w16q[DD * DD];
__device__ __half g_w16kv[1024 * DD];
__device__ __half g_w16o[DD * DD];

__device__ __half g_ct16[BB * TQ * DD];

// ======================= streams/events (static init) ========================
struct AsyncRes {
    cudaStream_t s1, s2;
    cudaEvent_t fork, e_wkv, e_q, e_trigk, e_misc, e_kv, j1;
    AsyncRes() {
        cudaStreamCreateWithFlags(&s1, cudaStreamNonBlocking);
        cudaStreamCreateWithFlags(&s2, cudaStreamNonBlocking);
        cudaEventCreateWithFlags(&fork, cudaEventDisableTiming);
        cudaEventCreateWithFlags(&e_wkv, cudaEventDisableTiming);
        cudaEventCreateWithFlags(&e_q, cudaEventDisableTiming);
        cudaEventCreateWithFlags(&e_trigk, cudaEventDisableTiming);
        cudaEventCreateWithFlags(&e_misc, cudaEventDisableTiming);
        cudaEventCreateWithFlags(&e_kv, cudaEventDisableTiming);
        cudaEventCreateWithFlags(&j1, cudaEventDisableTiming);
    }
};
static AsyncRes g_ar;

// ======================= small helpers =======================================
__device__ __forceinline__ uint32_t smem_u32(const void* p) {
    uint32_t a;
    asm("{ .reg .u64 t; cvta.to.shared.u64 t, %1; cvt.u32.u64 %0, t; }" : "=r"(a) : "l"(p));
    return a;
}
__device__ __forceinline__ void cp16(void* s, const void* g) {
    asm volatile("cp.async.cg.shared.global [%0], [%1], 16;"
                 :: "r"(smem_u32(s)), "l"(g));
}
#define CP_COMMIT() asm volatile("cp.async.commit_group;")
#define CP_WAIT0() asm volatile("cp.async.wait_group 0;")

__device__ __forceinline__ void ldm_x4(uint32_t* r, uint32_t addr) {
    asm volatile("ldmatrix.sync.aligned.m8n8.x4.shared.b16 {%0,%1,%2,%3}, [%4];"
                 : "=r"(r[0]), "=r"(r[1]), "=r"(r[2]), "=r"(r[3]) : "r"(addr));
}
__device__ __forceinline__ void ldm_x4_t(uint32_t* r, uint32_t addr) {
    asm volatile("ldmatrix.sync.aligned.m8n8.x4.trans.shared.b16 {%0,%1,%2,%3}, [%4];"
                 : "=r"(r[0]), "=r"(r[1]), "=r"(r[2]), "=r"(r[3]) : "r"(addr));
}
__device__ __forceinline__ void mma16816h(float* c, const uint32_t* a, uint32_t b0, uint32_t b1) {
    asm volatile("mma.sync.aligned.m16n8k16.row.col.f32.f16.f16.f32 "
                 "{%0,%1,%2,%3}, {%4,%5,%6,%7}, {%8,%9}, {%0,%1,%2,%3};"
                 : "+f"(c[0]), "+f"(c[1]), "+f"(c[2]), "+f"(c[3])
                 : "r"(a[0]), "r"(a[1]), "r"(a[2]), "r"(a[3]), "r"(b0), "r"(b1));
}
__device__ __forceinline__ uint32_t pack_h16(__half x, __half y) {
    uint16_t a = *(uint16_t*)&x, b = *(uint16_t*)&y;
    return (uint32_t)a | ((uint32_t)b << 16);
}
__device__ __forceinline__ uint32_t ex2_f16x2(float x, float y) {
    uint32_t pk, r;
    asm("cvt.rn.f16x2.f32 %0, %1, %2;" : "=r"(pk) : "f"(y), "f"(x));
    asm("ex2.approx.f16x2 %0, %1;" : "=r"(r) : "r"(pk));
    return r;
}
__device__ __forceinline__ float ex2f(float x) {
    float r;
    asm("ex2.approx.f32 %0, %1;" : "=f"(r) : "f"(x));
    return r;
}
__device__ __forceinline__ float2 unpack_h2(uint32_t v) {
    __half2 h = *reinterpret_cast<__half2*>(&v);
    return __half22float2(h);
}

// ======================= conversion kernels ==================================
__global__ void cvt_f16(const float* __restrict__ in, __half* __restrict__ h, int n) {
    int i = blockIdx.x * blockDim.x + threadIdx.x;
    if (i >= n) return;
    h[i] = __float2half(in[i]);
}

__global__ void splitT_h16(const float* __restrict__ in, __half* __restrict__ h,
                           int K, int N) {
    __shared__ float t[32][33];
    int tid = threadIdx.x;
    int kb = blockIdx.x * 32, nb = blockIdx.y * 32;
#pragma unroll
    for (int i = 0; i < 4; i++) {
        int e = tid + i * 256;
        int k = e >> 5, n = e & 31;
        t[k][n] = in[(size_t)(kb + k) * N + nb + n];
    }
    __syncthreads();
#pragma unroll
    for (int i = 0; i < 2; i++) {
        int e = tid + i * 256;
        int n = e >> 4, kp = (e & 15) * 2;
        uint32_t hi = pack_h16(__float2half(t[kp][n]), __float2half(t[kp + 1][n]));
        *(uint32_t*)&h[(size_t)(nb + n) * K + kb + kp] = hi;
    }
}

// ======================= 1-pass fp16 GEMM (64x64 warp tiles) =================
#define SP64 72
#define GEMM1_SMEM (2 * 2 * 128 * SP64 * 2)

__global__ __launch_bounds__(128, 2)
void gemm_h1(const __half* __restrict__ A, const __half* __restrict__ B,
             float* __restrict__ C, int M, int N, int K) {
    extern __shared__ __half sg1[];

    int tid = threadIdx.x;
    int lane = tid & 31, wid = tid >> 5;
    int wm = wid & 1, wn = wid >> 1;
    int m0 = blockIdx.y * 128;
    int n0 = blockIdx.x * 128;

    const int nit = K >> 6;

    auto issue = [&](int i) {
        __half* sb = sg1 + (i & 1) * 2 * 128 * SP64;
        const __half* Ag = A + (size_t)m0 * K + i * 64;
        const __half* Bg = B + (size_t)n0 * K + i * 64;
#pragma unroll
        for (int j = 0; j < 8; j++) {
            int id = tid + j * 128;
            int r = id >> 3, c8 = (id & 7) * 8;
            cp16(sb + r * SP64 + c8, Ag + (size_t)r * K + c8);
            cp16(sb + 128 * SP64 + r * SP64 + c8, Bg + (size_t)r * K + c8);
        }
    };

    float acc[4][8][4];
#pragma unroll
    for (int i = 0; i < 4; i++)
#pragma unroll
        for (int j = 0; j < 8; j++)
#pragma unroll
            for (int q = 0; q < 4; q++) acc[i][j][q] = 0.f;

    issue(0);
    CP_COMMIT();

    for (int i = 0; i < nit; i++) {
        CP_WAIT0();
        __syncthreads();
        if (i + 1 < nit) {
            issue(i + 1);
            CP_COMMIT();
        }
        __half* pA = sg1 + (i & 1) * 2 * 128 * SP64;
        __half* pB = pA + 128 * SP64;

#pragma unroll
        for (int ks = 0; ks < 64; ks += 16) {
            uint32_t ah[4][4], bh[4][4];
#pragma unroll
            for (int mt = 0; mt < 4; mt++) {
                int off = (wm * 64 + mt * 16 + (lane & 15)) * SP64 + ks + (lane >> 4) * 8;
                ldm_x4(ah[mt], smem_u32(pA + off));
            }
#pragma unroll
            for (int g = 0; g < 4; g++) {
                int boff = (wn * 64 + g * 16 + ((lane >> 4) << 3) + (lane & 7)) * SP64 +
                           ks + ((lane >> 3) & 1) * 8;
                ldm_x4(bh[g], smem_u32(pB + boff));
            }
#pragma unroll
            for (int g = 0; g < 4; g++)
#pragma unroll
                for (int pr = 0; pr < 2; pr++)
#pragma unroll
                    for (int mt = 0; mt < 4; mt++)
                        mma16816h(acc[mt][g * 2 + pr], ah[mt], bh[g][pr * 2], bh[g][pr * 2 + 1]);
        }
    }

#pragma unroll
    for (int mt = 0; mt < 4; mt++) {
        int r = m0 + wm * 64 + mt * 16 + (lane >> 2);
#pragma unroll
        for (int nt = 0; nt < 8; nt++) {
            int cidx = n0 + wn * 64 + nt * 8 + (lane & 3) * 2;
            *(float2*)&C[(size_t)r * N + cidx] = make_float2(acc[mt][nt][0], acc[mt][nt][1]);
            *(float2*)&C[(size_t)(r + 8) * N + cidx] = make_float2(acc[mt][nt][2], acc[mt][nt][3]);
        }
    }
}

// ======================= RoPE / transpose ====================================
__global__ void freq_kernel(double* __restrict__ invf) {
    int d = threadIdx.x;
    if (d < 64) invf[d] = pow(10000.0, -(double)d / 64.0);
}

__global__ void trig_kernel(const int* __restrict__ pos, const double* __restrict__ invf,
                            float2* __restrict__ out, int total) {
    int i = blockIdx.x * blockDim.x + threadIdx.x;
    if (i >= total) return;
    int d = i & 63;
    int bt = i >> 6;
    double ang = (double)pos[bt] * invf[d];
    double k = rint(ang * 0.15915494309189535);
    double r = fma(-k, 6.283185307179586, ang);
    r = fma(-k, 2.4492935982947064e-16, r);
    float rf = (float)r;
    float s, c;
    sincosf(rf, &s, &c);
    out[i] = make_float2(s, c);
}

// Fused K rope + V transpose from tmp2 (stride 1024: K cols 0-511, V cols 512-1023)
__global__ void ropekv16(const float* __restrict__ in, const float2* __restrict__ trig,
                         __half* __restrict__ k16, __half* __restrict__ v16) {
    int idx = blockIdx.x * blockDim.x + threadIdx.x;
    int total = BB * TKV * HKV * 64;
    if (idx >= total) return;
    int d = idx & 63;
    int h = (idx >> 6) & 3;
    int bt = idx >> 8;
    int b = bt / TKV, t = bt % TKV;

    const float* row = in + (size_t)bt * 1024;
    float x1 = row[h * HD + d];
    float x2 = row[h * HD + d + 64];
    float2 sc = trig[(size_t)bt * 64 + d];
    size_t o = ((size_t)(b * HKV + h) * TKV + t) * HD + d;
    k16[o] = __float2half(x1 * sc.y - x2 * sc.x);
    k16[o + 64] = __float2half(x1 * sc.x + x2 * sc.y);

    float v1 = row[512 + h * HD + d];
    float v2 = row[512 + h * HD + d + 64];
    v16[o] = __float2half(v1);
    v16[o + 64] = __float2half(v2);
}

// ======================= Flash attention (fused Q-rope) ======================
// Q read as fp32 proj output + trig, rope applied while filling sQ.
#define RS 136
#define ATTN2_SMEM ((128 * RS + 2 * 2 * 64 * RS) * 2)

__global__ __launch_bounds__(256, 1)
void attn_mma(const float* __restrict__ Qf, const float2* __restrict__ trigq,
              const __half* __restrict__ K16, const __half* __restrict__ V16,
              __half* __restrict__ C16) {
    extern __shared__ __half smh[];
    __half* sQ = smh;
    __half* sKV = smh + 128 * RS;

    int tid = threadIdx.x, lane = tid & 31, wm = tid >> 5;
    int qt = gridDim.x - 1 - blockIdx.x;   // heavy tiles first
    int h = blockIdx.y, b = blockIdx.z;
    int qs0 = qt * 128;
    int bT = b * TQ;
    size_t kvoff = (size_t)(b * HKV + (h >> 2)) * TKV * HD;
    const __half* k_b = K16 + kvoff;
    const __half* v_b = V16 + kvoff;

    auto issueKV = [&](int jt) {
        __half* base = sKV + (jt & 1) * 2 * 64 * RS;
        const __half* kk = k_b + (size_t)jt * 64 * HD;
        const __half* vv = v_b + (size_t)jt * 64 * HD;
#pragma unroll
        for (int i = 0; i < 4; i++) {
            int c = tid + i * 256;
            int r = c >> 4, c8 = (c & 15) * 8;
            int so = r * RS + c8;
            size_t go = (size_t)r * HD + c8;
            cp16(base + so, kk + go);
            cp16(base + 64 * RS + so, vv + go);
        }
    };

    issueKV(0);
    CP_COMMIT();

    // ---- Q load with fused rope (fp32 -> fp16) ----
    {
        const float* qbase = Qf + (size_t)(bT + qs0) * DD + h * HD;
#pragma unroll 8
        for (int i = 0; i < 32; i++) {
            int idx = tid + i * 256;
            int d = idx & 63, r = idx >> 6;
            const float* rp = qbase + (size_t)r * DD;
            float x1 = rp[d], x2 = rp[d + 64];
            float2 sc = trigq[(size_t)(bT + qs0 + r) * 64 + d];
            sQ[r * RS + d] = __float2half(x1 * sc.y - x2 * sc.x);
            sQ[r * RS + d + 64] = __float2half(x1 * sc.x + x2 * sc.y);
        }
    }

    float o[16][4];
#pragma unroll
    for (int i = 0; i < 16; i++)
#pragma unroll
        for (int j = 0; j < 4; j++) o[i][j] = 0.f;
    float m0 = -1e30f, m1 = -1e30f, l0 = 0.f, l1 = 0.f;

    const float scale2 = 0.08838834764831845f * 1.4426950408889634f;
    int row0 = qs0 + wm * 16 + (lane >> 2);
    int ntiles = 2 * (qt + 1);

    for (int jt = 0; jt < ntiles; jt++) {
        CP_WAIT0();
        __syncthreads();
        if (jt + 1 < ntiles) {
            issueKV(jt + 1);
            CP_COMMIT();
        }
        __half* kk = sKV + (jt & 1) * 2 * 64 * RS;
        __half* vv = kk + 64 * RS;

        float s_[8][4];
#pragma unroll
        for (int i = 0; i < 8; i++)
#pragma unroll
            for (int j = 0; j < 4; j++) s_[i][j] = 0.f;

#pragma unroll
        for (int kt = 0; kt < 8; kt++) {
            uint32_t ah[4], bh[4][4];
            int arow = (wm * 16 + (lane & 15)) * RS + kt * 16 + (lane >> 4) * 8;
            ldm_x4(ah, smem_u32(&sQ[arow]));
#pragma unroll
            for (int g = 0; g < 4; g++) {
                int boff = (g * 16 + ((lane >> 4) << 3) + (lane & 7)) * RS +
                           kt * 16 + ((lane >> 3) & 1) * 8;
                ldm_x4(bh[g], smem_u32(&kk[boff]));
            }
#pragma unroll
            for (int g = 0; g < 4; g++)
#pragma unroll
                for (int pr = 0; pr < 2; pr++)
                    mma16816h(s_[g * 2 + pr], ah, bh[g][pr * 2], bh[g][pr * 2 + 1]);
        }

#pragma unroll
        for (int nt = 0; nt < 8; nt++)
#pragma unroll
            for (int c = 0; c < 4; c++) s_[nt][c] *= scale2;
        if (jt * 64 + 63 > row0) {
#pragma unroll
            for (int nt = 0; nt < 8; nt++) {
                int colb = jt * 64 + nt * 8 + (lane & 3) * 2;
                if (colb > row0) s_[nt][0] = -1e30f;
                if (colb + 1 > row0) s_[nt][1] = -1e30f;
                if (colb > row0 + 8) s_[nt][2] = -1e30f;
                if (colb + 1 > row0 + 8) s_[nt][3] = -1e30f;
            }
        }

        float tm0 = -1e30f, tm1 = -1e30f;
#pragma unroll
        for (int nt = 0; nt < 8; nt++) {
            tm0 = fmaxf(tm0, fmaxf(s_[nt][0], s_[nt][1]));
            tm1 = fmaxf(tm1, fmaxf(s_[nt][2], s_[nt][3]));
        }
        tm0 = fmaxf(tm0, __shfl_xor_sync(0xffffffffu, tm0, 1));
        tm0 = fmaxf(tm0, __shfl_xor_sync(0xffffffffu, tm0, 2));
        tm1 = fmaxf(tm1, __shfl_xor_sync(0xffffffffu, tm1, 1));
        tm1 = fmaxf(tm1, __shfl_xor_sync(0xffffffffu, tm1, 2));
        float nm0 = fmaxf(m0, tm0), nm1 = fmaxf(m1, tm1);
        float a0 = ex2f(m0 - nm0), a1 = ex2f(m1 - nm1);

        uint32_t pf[4][4];
        float rs0 = 0.f, rs1 = 0.f;
#pragma unroll
        for (int kt = 0; kt < 4; kt++) {
            pf[kt][0] = ex2_f16x2(s_[2 * kt][0] - nm0, s_[2 * kt][1] - nm0);
            pf[kt][1] = ex2_f16x2(s_[2 * kt][2] - nm1, s_[2 * kt][3] - nm1);
            pf[kt][2] = ex2_f16x2(s_[2 * kt + 1][0] - nm0, s_[2 * kt + 1][1] - nm0);
            pf[kt][3] = ex2_f16x2(s_[2 * kt + 1][2] - nm1, s_[2 * kt + 1][3] - nm1);
            float2 f;
            f = unpack_h2(pf[kt][0]); rs0 += f.x + f.y;
            f = unpack_h2(pf[kt][2]); rs0 += f.x + f.y;
            f = unpack_h2(pf[kt][1]); rs1 += f.x + f.y;
            f = unpack_h2(pf[kt][3]); rs1 += f.x + f.y;
        }
        rs0 += __shfl_xor_sync(0xffffffffu, rs0, 1);
        rs0 += __shfl_xor_sync(0xffffffffu, rs0, 2);
        rs1 += __shfl_xor_sync(0xffffffffu, rs1, 1);
        rs1 += __shfl_xor_sync(0xffffffffu, rs1, 2);
        l0 = l0 * a0 + rs0;
        l1 = l1 * a1 + rs1;
        m0 = nm0;
        m1 = nm1;
#pragma unroll
        for (int nt = 0; nt < 16; nt++) {
            o[nt][0] *= a0;
            o[nt][1] *= a0;
            o[nt][2] *= a1;
            o[nt][3] *= a1;
        }

#pragma unroll
        for (int kt = 0; kt < 4; kt++) {
            int vrow = kt * 16 + (lane & 7) + ((lane >> 3) & 1) * 8;
#pragma unroll
            for (int g = 0; g < 8; g++) {
                uint32_t vhf[4];
                int voff = vrow * RS + g * 16 + (lane >> 4) * 8;
                ldm_x4_t(vhf, smem_u32(&vv[voff]));
                mma16816h(o[2 * g], pf[kt], vhf[0], vhf[1]);
                mma16816h(o[2 * g + 1], pf[kt], vhf[2], vhf[3]);
            }
        }
    }

    float li0 = 1.0f / l0, li1 = 1.0f / l1;
#pragma unroll
    for (int nt = 0; nt < 16; nt++) {
        int col = nt * 8 + (lane & 3) * 2;
        size_t ad0 = ((size_t)(bT + row0) * HQ + h) * HD + col;
        size_t ad1 = ((size_t)(bT + row0 + 8) * HQ + h) * HD + col;
        *(uint32_t*)&C16[ad0] =
            pack_h16(__float2half(o[nt][0] * li0), __float2half(o[nt][1] * li0));
        *(uint32_t*)&C16[ad1] =
            pack_h16(__float2half(o[nt][2] * li1), __float2half(o[nt][3] * li1));
    }
}

// ======================= launch ==============================================
extern "C" void kernel_launch(void* const* d_in, const int* in_sizes, int n_in,
                              void* d_out, int out_size) {
    const float* Xq  = (const float*)d_in[0];
    const float* Xkv = (const float*)d_in[1];
    const float* Wq  = (const float*)d_in[2];
    const float* Wk  = (const float*)d_in[3];
    const float* Wv  = (const float*)d_in[4];
    const float* Wo  = (const float*)d_in[5];
    const int* qpos  = (const int*)d_in[6];
    const int* kpos  = (const int*)d_in[7];
    float* out = (float*)d_out;

    void* p;
    cudaGetSymbolAddress(&p, g_tmp); float* tmp = (float*)p;
    cudaGetSymbolAddress(&p, g_tmp2); float* tmp2 = (float*)p;
    cudaGetSymbolAddress(&p, g_trigq); float2* trigq = (float2*)p;
    cudaGetSymbolAddress(&p, g_trigk); float2* trigk = (float2*)p;
    cudaGetSymbolAddress(&p, g_invf); double* invf = (double*)p;
    __half *k16, *v16, *xq16, *xk16, *w16q, *w16kv, *w16o, *ct16;
    cudaGetSymbolAddress(&p, g_k16); k16 = (__half*)p;
    cudaGetSymbolAddress(&p, g_v16); v16 = (__half*)p;
    cudaGetSymbolAddress(&p, g_xq16); xq16 = (__half*)p;
    cudaGetSymbolAddress(&p, g_xk16); xk16 = (__half*)p;
    cudaGetSymbolAddress(&p, g_w16q); w16q = (__half*)p;
    cudaGetSymbolAddress(&p, g_w16kv); w16kv = (__half*)p;
    cudaGetSymbolAddress(&p, g_w16o); w16o = (__half*)p;
    cudaGetSymbolAddress(&p, g_ct16); ct16 = (__half*)p;

    cudaFuncSetAttribute(attn_mma, cudaFuncAttributeMaxDynamicSharedMemorySize, ATTN2_SMEM);
    cudaFuncSetAttribute(gemm_h1, cudaFuncAttributeMaxDynamicSharedMemorySize, GEMM1_SMEM);

    const int M = BB * TQ;  // 4096
    int nX = BB * TQ * DD;
    cudaStream_t s0 = 0, s1 = g_ar.s1, s2 = g_ar.s2;

    // ---- fork ----
    cudaEventRecord(g_ar.fork, s0);
    cudaStreamWaitEvent(s1, g_ar.fork, 0);
    cudaStreamWaitEvent(s2, g_ar.fork, 0);

    // head: only cvt(Xkv)+Wk/Wv-T gate the first GEMM
    cvt_f16<<<(nX + 255) / 256, 256, 0, s0>>>(Xkv, xk16, nX);
    splitT_h16<<<dim3(DD / 32, 512 / 32), 256, 0, s2>>>(Wk, w16kv, DD, 512);
    splitT_h16<<<dim3(DD / 32, 512 / 32), 256, 0, s2>>>(Wv, w16kv + 512 * DD, DD, 512);
    cudaEventRecord(g_ar.e_wkv, s2);
    cudaStreamWaitEvent(s0, g_ar.e_wkv, 0);

    // ---- KV projection (first tensor op) ----                 (profiled slot)
    gemm_h1<<<dim3(1024 / 128, M / 128), 128, GEMM1_SMEM, s0>>>(xk16, w16kv, tmp2, M, 1024, DD);
    cudaEventRecord(g_ar.e_kv, s0);

    // s1: Q-side conversions (run under KV-GEMM)
    cvt_f16<<<(nX + 255) / 256, 256, 0, s1>>>(Xq, xq16, nX);
    splitT_h16<<<dim3(DD / 32, DD / 32), 256, 0, s1>>>(Wq, w16q, DD, DD);
    cudaEventRecord(g_ar.e_q, s1);

    // s2: trig/Wo (input-only)
    freq_kernel<<<1, 64, 0, s2>>>(invf);
    trig_kernel<<<(BB * TKV * 64 + 255) / 256, 256, 0, s2>>>(kpos, invf, trigk, BB * TKV * 64);
    cudaEventRecord(g_ar.e_trigk, s2);
    trig_kernel<<<(BB * TQ * 64 + 255) / 256, 256, 0, s2>>>(qpos, invf, trigq, BB * TQ * 64);
    splitT_h16<<<dim3(HQ * HD / 32, DD / 32), 256, 0, s2>>>(Wo, w16o, HQ * HD, DD);
    cudaEventRecord(g_ar.e_misc, s2);

    // s1: fused K-rope + V-transpose, overlapping Q-GEMM
    cudaStreamWaitEvent(s1, g_ar.e_kv, 0);
    cudaStreamWaitEvent(s1, g_ar.e_trigk, 0);
    ropekv16<<<(BB * TKV * HKV * 64 + 255) / 256, 256, 0, s1>>>(tmp2, trigk, k16, v16);
    cudaEventRecord(g_ar.j1, s1);

    // ---- Q projection ----
    cudaStreamWaitEvent(s0, g_ar.e_q, 0);
    gemm_h1<<<dim3(DD / 128, M / 128), 128, GEMM1_SMEM, s0>>>(xq16, w16q, tmp, M, DD, DD);

    // ---- attention (fused Q rope) ----
    cudaStreamWaitEvent(s0, g_ar.j1, 0);
    cudaStreamWaitEvent(s0, g_ar.e_misc, 0);
    attn_mma<<<dim3(TQ / 128, HQ, BB), 256, ATTN2_SMEM, s0>>>(tmp, trigq, k16, v16, ct16);

    // ---- output projection ----
    gemm_h1<<<dim3(DD / 128, M / 128), 128, GEMM1_SMEM, s0>>>(ct16, w16o, out, M, DD, DD);
}